// round 13
// baseline (speedup 1.0000x reference)
#include <cuda_runtime.h>
#include <cuda_bf16.h>
#include <cstdint>
#include <math.h>

#define NB 256
#define NS 32
#define NL 32
#define ND 256
#define NE 64
#define KBIG 768          // Bt columns: [Hi | Lo | Hi-dup(unused)]

// ===================== scratch (device globals; no runtime alloc) =====================
__device__ float g_enc[NB*NS*ND];            // enc[b,s,d]
__device__ float g_eW [NB*NS*ND];            // enc @ W
__device__ float g_kV [NB*NE*ND];            // keys @ V
__device__ int   g_act[NB*NS];
__device__ float g_dek[NB*NE*NS];            // dot(enc_s, keys_row), [row][s]
__device__ __nv_bfloat16 g_Ut[ND*KBIG];      // U^T  [Hi|Lo|Hi]
__device__ __nv_bfloat16 g_Vt[ND*KBIG];      // V^T  [Hi|Lo|Hi]
__device__ __nv_bfloat16 g_Wt[ND*KBIG];      // W^T  [Hi|Lo|Hi]
__device__ __nv_bfloat16 g_kyhi[NB*NE*ND];   // keys split
__device__ __nv_bfloat16 g_kylo[NB*NE*ND];
__device__ __nv_bfloat16 g_enhi[NB*NS*ND];   // enc split
__device__ __nv_bfloat16 g_enlo[NB*NS*ND];

// ===================== PTX wrappers =====================
__device__ __forceinline__ uint32_t smem_u32(const void* p) {
    uint32_t a;
    asm("{ .reg .u64 t; cvta.to.shared.u64 t, %1; cvt.u32.u64 %0, t; }" : "=r"(a) : "l"(p));
    return a;
}
__device__ __forceinline__ void cpa16(uint32_t dst, const void* src) {
    asm volatile("cp.async.cg.shared.global [%0], [%1], 16;" :: "r"(dst), "l"(src));
}
#define CP_COMMIT() asm volatile("cp.async.commit_group;" ::: "memory")
#define CP_WAIT1()  asm volatile("cp.async.wait_group 1;"  ::: "memory")
#define CP_WAIT0()  asm volatile("cp.async.wait_group 0;"  ::: "memory")

__device__ __forceinline__ void ldsm_x4(uint32_t* r, uint32_t addr) {
    asm volatile("ldmatrix.sync.aligned.m8n8.x4.shared.b16 {%0,%1,%2,%3}, [%4];"
        : "=r"(r[0]), "=r"(r[1]), "=r"(r[2]), "=r"(r[3]) : "r"(addr));
}
__device__ __forceinline__ void mma_bf16(float* d, const uint32_t* a, const uint32_t* b) {
    asm volatile("mma.sync.aligned.m16n8k16.row.col.f32.bf16.bf16.f32 "
        "{%0,%1,%2,%3}, {%4,%5,%6,%7}, {%8,%9}, {%0,%1,%2,%3};"
        : "+f"(d[0]), "+f"(d[1]), "+f"(d[2]), "+f"(d[3])
        : "r"(a[0]), "r"(a[1]), "r"(a[2]), "r"(a[3]), "r"(b[0]), "r"(b[1]));
}

// ===================== steps smem layout (64-row CTA, 2 CTAs/SM) =====================
#define SM_GATE 0                           // 64 floats
#define SM_RSQ  256
#define SM_GN   512
#define SM_ACTS 768
#define SM_RS4  1024                        // [4][64] floats
#define SM_DV4  2048
#define SM_DH4  3072
#define SM_AHI  4096                        // 64 rows * 512B (xor-swizzled) = 32768
#define SM_ALO  (4096 + 32768)
#define SM_RING (4096 + 65536)              // 69632
#define STG     20480
#define SMEM_STEPS (SM_RING + 2*STG)        // 110592 (<= 113.5KB, 2 CTAs/SM)

// ===================== encode (vectorized, + bf16 split fold-in) =====================
__global__ __launch_bounds__(256)
void encode_kernel(const int* __restrict__ tok, const float* __restrict__ mask,
                   const float* __restrict__ emb) {
    __shared__ float4 red[4][64];
    const int bs = blockIdx.x, tid = threadIdx.x;
    const int lg = tid >> 6, d4 = tid & 63;
    const int*   t = tok  + (size_t)bs*NL;
    const float* m = mask + (size_t)bs*NL;

    if (tid < 32) {
        float mv = m[tid];
        #pragma unroll
        for (int o = 16; o > 0; o >>= 1) mv += __shfl_xor_sync(0xffffffffu, mv, o);
        if (tid == 0) g_act[bs] = (mv > 0.f) ? 1 : 0;
    }

    float4 acc = make_float4(0.f, 0.f, 0.f, 0.f);
    #pragma unroll
    for (int i = 0; i < 8; i++) {
        int l = lg*8 + i;
        float mv = __ldg(m + l);
        int   tv = __ldg(t + l);
        float4 e = __ldg((const float4*)(emb + (size_t)tv*ND) + d4);
        acc.x += mv*e.x; acc.y += mv*e.y; acc.z += mv*e.z; acc.w += mv*e.w;
    }
    red[lg][d4] = acc;
    __syncthreads();
    if (lg == 0) {
        float4 a = red[0][d4], b = red[1][d4], c = red[2][d4], d = red[3][d4];
        float4 v = make_float4(a.x+b.x+c.x+d.x, a.y+b.y+c.y+d.y,
                               a.z+b.z+c.z+d.z, a.w+b.w+c.w+d.w);
        size_t off = (size_t)bs*ND + d4*4;
        *(float4*)(g_enc + off) = v;
        float vv[4] = {v.x, v.y, v.z, v.w};
        __nv_bfloat16 hb[4], lb[4];
        #pragma unroll
        for (int i = 0; i < 4; i++) {
            hb[i] = __float2bfloat16(vv[i]);
            lb[i] = __float2bfloat16(vv[i] - __bfloat162float(hb[i]));
        }
        *(__nv_bfloat162*)(g_enhi + off)     = __nv_bfloat162(hb[0], hb[1]);
        *(__nv_bfloat162*)(g_enhi + off + 2) = __nv_bfloat162(hb[2], hb[3]);
        *(__nv_bfloat162*)(g_enlo + off)     = __nv_bfloat162(lb[0], lb[1]);
        *(__nv_bfloat162*)(g_enlo + off + 2) = __nv_bfloat162(lb[2], lb[3]);
    }
}

// ===================== prep: Mt[n][k] = [Mhi^T | Mlo^T | Mhi^T] =====================
__global__ void prep_bt_all(const float* __restrict__ U, const float* __restrict__ V,
                            const float* __restrict__ W) {
    int n = blockIdx.x & 255, which = blockIdx.x >> 8, k = threadIdx.x;
    const float* M = (which == 0) ? U : (which == 1) ? V : W;
    __nv_bfloat16* out = (which == 0) ? g_Ut : (which == 1) ? g_Vt : g_Wt;
    float v = M[(size_t)k*ND + n];
    __nv_bfloat16 hi = __float2bfloat16(v);
    __nv_bfloat16 lo = __float2bfloat16(v - __bfloat162float(hi));
    out[(size_t)n*KBIG + k]       = hi;
    out[(size_t)n*KBIG + 256 + k] = lo;
    out[(size_t)n*KBIG + 512 + k] = hi;
}

// ===================== split fp32 -> bf16 hi/lo (keys only) =====================
__global__ void split_kernel(const float* __restrict__ keys) {
    int i = blockIdx.x * blockDim.x + threadIdx.x;
    float v = keys[i];
    __nv_bfloat16 h = __float2bfloat16(v);
    g_kyhi[i] = h;
    g_kylo[i] = __float2bfloat16(v - __bfloat162float(h));
}

// ===================== persistent fused kernel: kV + eW + 32-step recurrence =========
// 64-row CTAs, 256 threads, 2 CTAs per SM for latency overlap.
__global__ void __launch_bounds__(256, 2)
steps_kernel(const float* __restrict__ keys, float* __restrict__ h) {
    extern __shared__ char smem[];
    const uint32_t sb = smem_u32(smem);
    const int tid    = threadIdx.x;
    const int lane   = tid & 31;
    const int wid    = tid >> 5;          // 0..7
    const int warp_m = wid >> 2;          // 0..1 -> 32 rows each
    const int warp_n = wid & 3;           // 0..3 -> 64 cols each
    const int rowBase = blockIdx.x * 64;
    const int b = blockIdx.x;             // exactly one b per CTA (NE = 64)
    const int CTOT = 32 + (NS - 1) * 16;  // 16 Vt + 16 Wt + 496 Ut = 528

    float* gs   = (float*)(smem + SM_GATE);
    float* rs   = (float*)(smem + SM_RSQ);
    float* gn   = (float*)(smem + SM_GN);
    int*   acts = (int*)  (smem + SM_ACTS);

    // ---- B stream: chunk c; pair p = (c&15)>>1, kk = p*32; even=Hi, odd=Lo; slot c&1
    auto load_chunk = [&](int c) {
        int q = c & 15;
        int kk = (q >> 1) * 32;
        const __nv_bfloat16* mat = (c < 16) ? g_Vt : (c < 32) ? g_Wt : g_Ut;
        const __nv_bfloat16* bsrc = mat + ((q & 1) ? (256 + kk) : kk);
        uint32_t base = sb + SM_RING + (uint32_t)(c & 1)*STG;
        #pragma unroll
        for (int i = 0; i < 4; i++) {          // 256 rows x 4 segs of 16B
            int idx = tid + i*256, row = idx >> 2, seg = idx & 3;
            cpa16(base + row*80 + seg*16, bsrc + (size_t)row*KBIG + seg*8);
        }
    };

    // ---- A smem loader (plain LDG/STS); nrows via niter (8 -> 64 rows, 4 -> 32) ----
    auto load_A = [&](const __nv_bfloat16* srcHi, const __nv_bfloat16* srcLo, int niter) {
        for (int i = 0; i < niter; i++) {
            int idx = tid + i*256;
            int row = idx >> 5, seg = idx & 31;
            uint32_t dst = (uint32_t)row*512 + (uint32_t)((seg ^ (row & 7))*16);
            *(uint4*)(smem + SM_AHI + dst) = *(const uint4*)(srcHi + (size_t)row*ND + seg*8);
            *(uint4*)(smem + SM_ALO + dst) = *(const uint4*)(srcLo + (size_t)row*ND + seg*8);
        }
    };

    // prime: chunk 0 in flight
    int cnext = 0;
    load_chunk(cnext); CP_COMMIT(); cnext++;

    // ---------- phase 0: g_dek[row][s] = dot(enc_s, keys_row) (overlaps prefetch) ----
    {
        int r = tid >> 2, part = tid & 3;     // r 0..63
        int grow = rowBase + r;
        float4 ky[16];
        const float4* kp = (const float4*)(keys + (size_t)grow*ND + part*64);
        #pragma unroll
        for (int i = 0; i < 16; i++) ky[i] = kp[i];
        for (int s = 0; s < NS; s++) {
            const float4* ep = (const float4*)(g_enc + ((size_t)b*NS + s)*ND + part*64);
            float d = 0.f;
            #pragma unroll
            for (int i = 0; i < 16; i++) {
                float4 e = ep[i];
                d += ky[i].x*e.x + ky[i].y*e.y + ky[i].z*e.z + ky[i].w*e.w;
            }
            d += __shfl_xor_sync(0xffffffffu, d, 1);
            d += __shfl_xor_sync(0xffffffffu, d, 2);
            if (part == 0) g_dek[(size_t)grow*NS + s] = d;
        }
        if (tid < 64) gn[tid] = 0.f;
    }

    // ---- per-lane constants ----
    const int lane7 = lane & 7;
    const int sel2  = lane >> 4;
    const uint32_t arow = (uint32_t)(warp_m*32 + ((lane >> 3) & 1)*8 + lane7) * 512;
    const uint32_t boff4 = (uint32_t)(((lane >> 4)*8 + lane7)*80 + ((lane >> 3) & 1)*16);
    const int r7 = (lane >> 2) & 7;
    const uint32_t ebyte = (uint32_t)((lane & 3)*4);

    float acc[2][8][4];
    uint32_t ahc[2][8];                   // A-hi fragments carried even->odd chunk
    auto zero_acc = [&]() {
        #pragma unroll
        for (int mt = 0; mt < 2; mt++)
            #pragma unroll
            for (int nt = 0; nt < 8; nt++)
                #pragma unroll
                for (int q = 0; q < 4; q++) acc[mt][nt][q] = 0.f;
    };

    auto compute = [&](int c) {
        const int q = c & 15;
        const int kkidx = q >> 1;
        const bool isHi = !(q & 1);
        uint32_t bB = sb + SM_RING + (uint32_t)(c & 1)*STG + (warp_n*64)*80 + boff4;
        const int kseg0 = kkidx*4 + sel2;
        #pragma unroll
        for (int k2 = 0; k2 < 2; ++k2) {
            const uint32_t kb = (uint32_t)k2*32;
            uint32_t bq[16];
            #pragma unroll
            for (int np = 0; np < 4; np++) ldsm_x4(&bq[np*4], bB + np*1280 + kb);
            if (isHi) {
                const uint32_t seg = (uint32_t)((kseg0 + k2*2) ^ lane7) * 16;
                uint32_t aHa = sb + SM_AHI + arow + seg;
                ldsm_x4(&ahc[k2][0], aHa);
                ldsm_x4(&ahc[k2][4], aHa + 8192);     // +16 rows
                #pragma unroll
                for (int np = 0; np < 4; np++) {
                    mma_bf16(acc[0][2*np],   &ahc[k2][0], &bq[np*4]);
                    mma_bf16(acc[0][2*np+1], &ahc[k2][0], &bq[np*4+2]);
                    mma_bf16(acc[1][2*np],   &ahc[k2][4], &bq[np*4]);
                    mma_bf16(acc[1][2*np+1], &ahc[k2][4], &bq[np*4+2]);
                }
                uint32_t aLa = sb + SM_ALO + arow + seg;
                uint32_t al[8];
                ldsm_x4(al,     aLa);
                ldsm_x4(al + 4, aLa + 8192);
                #pragma unroll
                for (int np = 0; np < 4; np++) {
                    mma_bf16(acc[0][2*np],   al,     &bq[np*4]);
                    mma_bf16(acc[0][2*np+1], al,     &bq[np*4+2]);
                    mma_bf16(acc[1][2*np],   al + 4, &bq[np*4]);
                    mma_bf16(acc[1][2*np+1], al + 4, &bq[np*4+2]);
                }
            } else {
                #pragma unroll
                for (int np = 0; np < 4; np++) {
                    mma_bf16(acc[0][2*np],   &ahc[k2][0], &bq[np*4]);
                    mma_bf16(acc[0][2*np+1], &ahc[k2][0], &bq[np*4+2]);
                    mma_bf16(acc[1][2*np],   &ahc[k2][4], &bq[np*4]);
                    mma_bf16(acc[1][2*np+1], &ahc[k2][4], &bq[np*4+2]);
                }
            }
        }
    };

    // per-chunk schedule: sync -> issue(c+1) -> wait(c) -> compute(c)
    auto run16 = [&](int c0) {
        for (int i = 0; i < 16; ++i) {
            const int c = c0 + i;
            __syncthreads();                       // slot (c-1)&1 free across CTA
            if (cnext < CTOT && cnext == c + 1) { load_chunk(cnext); CP_COMMIT(); cnext++; }
            const int pend = cnext - 1 - c;
            if (pend >= 1) CP_WAIT1(); else CP_WAIT0();
            compute(c);
        }
    };

    // ---------- phase 1: kV = keys @ V for this CTA's 64 rows ----------
    load_A(g_kyhi + (size_t)rowBase*ND, g_kylo + (size_t)rowBase*ND, 8);
    zero_acc();
    run16(0);
    __syncthreads();
    #pragma unroll
    for (int mt = 0; mt < 2; mt++) {
        int rA = warp_m*32 + mt*16 + (lane >> 2);
        int rB = rA + 8;
        size_t gOA = (size_t)(rowBase + rA)*ND;
        size_t gOB = (size_t)(rowBase + rB)*ND;
        #pragma unroll
        for (int nt = 0; nt < 8; nt++) {
            int col = warp_n*64 + nt*8 + 2*(lane & 3);
            *(float2*)(g_kV + gOA + col) = make_float2(acc[mt][nt][0], acc[mt][nt][1]);
            *(float2*)(g_kV + gOB + col) = make_float2(acc[mt][nt][2], acc[mt][nt][3]);
        }
    }

    // ---------- phase 2: eW = enc @ W for this CTA's 32 enc rows ----------
    __syncthreads();                    // kV stores done before A tile overwritten
    load_A(g_enhi + (size_t)(b*32)*ND, g_enlo + (size_t)(b*32)*ND, 4);
    zero_acc();
    run16(16);
    __syncthreads();
    if (warp_m == 0) {
        #pragma unroll
        for (int mt = 0; mt < 2; mt++) {
            int rA = mt*16 + (lane >> 2);
            int rB = rA + 8;
            size_t gOA = (size_t)(b*32 + rA)*ND;
            size_t gOB = (size_t)(b*32 + rB)*ND;
            #pragma unroll
            for (int nt = 0; nt < 8; nt++) {
                int col = warp_n*64 + nt*8 + 2*(lane & 3);
                *(float2*)(g_eW + gOA + col) = make_float2(acc[mt][nt][0], acc[mt][nt][1]);
                *(float2*)(g_eW + gOB + col) = make_float2(acc[mt][nt][2], acc[mt][nt][3]);
            }
        }
    }

    // ---------- phase 3: the 32-step recurrence ----------
    for (int s = 0; s < NS; ++s) {
        const bool first = (s == 0);
        const bool last  = (s == NS - 1);
        __syncthreads();                // prior epilogue reads of gs/acts/rs done
        if (tid < 64) {
            int grow = rowBase + tid;
            gs[tid]   = 1.f / (1.f + expf(-(gn[tid] + g_dek[(size_t)grow*NS + s])));
            acts[tid] = g_act[b*NS + s];
        }

        zero_acc();

        if (!first) {
            run16(32 + (s - 1)*16);     // starts with its own __syncthreads
        } else {
            __syncthreads();
        }

        // ---------- epilogue pass 1 (h state from persistent smem) ----------
        const int sn = (s + 1 < NS) ? s + 1 : NS - 1;
        #pragma unroll
        for (int mt = 0; mt < 2; mt++) {
            int rA = warp_m*32 + mt*16 + (lane >> 2);
            int rB = rA + 8;
            int gA = rowBase + rA, gB = rowBase + rB;
            const float* kvA = g_kV + (size_t)gA*ND;
            const float* kvB = g_kV + (size_t)gB*ND;
            const float* ewR = g_eW  + ((size_t)b*NS + s )*ND;
            const float* enN = g_enc + ((size_t)b*NS + sn)*ND;
            float gateA = gs[rA], gateB = gs[rB];
            float sA = 0.f, sB = 0.f;
            float dVA = 0.f, dVB = 0.f, dHA = 0.f, dHB = 0.f;
            #pragma unroll
            for (int nt = 0; nt < 8; nt++) {
                int col = warp_n*64 + nt*8 + 2*(lane & 3);
                const uint32_t seg = (uint32_t)((warp_n*8 + nt) ^ r7) * 16;
                float2 en = *(const float2*)(enN + col);
                float2 ew = *(const float2*)(ewR + col);
                float2 kv, ho;
                kv = *(const float2*)(kvA + col);
                if (first) ho = make_float2(0.f, 0.f);
                else {
                    uint32_t offA = (uint32_t)rA*512 + seg + ebyte;
                    __nv_bfloat162 hb = *(__nv_bfloat162*)(smem + SM_AHI + offA);
                    __nv_bfloat162 lb = *(__nv_bfloat162*)(smem + SM_ALO + offA);
                    ho = make_float2(__bfloat162float(hb.x) + __bfloat162float(lb.x),
                                     __bfloat162float(hb.y) + __bfloat162float(lb.y));
                }
                float v0 = fmaxf(acc[mt][nt][0] + kv.x + ew.x, 0.f);
                float v1 = fmaxf(acc[mt][nt][1] + kv.y + ew.y, 0.f);
                float h0 = ho.x + gateA*v0, h1 = ho.y + gateA*v1;
                acc[mt][nt][0] = h0; acc[mt][nt][1] = h1;
                sA  += h0*h0 + h1*h1;
                dVA += en.x*h0 + en.y*h1;
                dHA += en.x*ho.x + en.y*ho.y;
                kv = *(const float2*)(kvB + col);
                if (first) ho = make_float2(0.f, 0.f);
                else {
                    uint32_t offB = (uint32_t)rB*512 + seg + ebyte;
                    __nv_bfloat162 hb = *(__nv_bfloat162*)(smem + SM_AHI + offB);
                    __nv_bfloat162 lb = *(__nv_bfloat162*)(smem + SM_ALO + offB);
                    ho = make_float2(__bfloat162float(hb.x) + __bfloat162float(lb.x),
                                     __bfloat162float(hb.y) + __bfloat162float(lb.y));
                }
                float w0 = fmaxf(acc[mt][nt][2] + kv.x + ew.x, 0.f);
                float w1 = fmaxf(acc[mt][nt][3] + kv.y + ew.y, 0.f);
                float h2 = ho.x + gateB*w0, h3 = ho.y + gateB*w1;
                acc[mt][nt][2] = h2; acc[mt][nt][3] = h3;
                sB  += h2*h2 + h3*h3;
                dVB += en.x*h2 + en.y*h3;
                dHB += en.x*ho.x + en.y*ho.y;
            }
            #pragma unroll
            for (int o = 1; o <= 2; o <<= 1) {
                sA  += __shfl_xor_sync(0xffffffffu, sA,  o);
                sB  += __shfl_xor_sync(0xffffffffu, sB,  o);
                dVA += __shfl_xor_sync(0xffffffffu, dVA, o);
                dVB += __shfl_xor_sync(0xffffffffu, dVB, o);
                dHA += __shfl_xor_sync(0xffffffffu, dHA, o);
                dHB += __shfl_xor_sync(0xffffffffu, dHB, o);
            }
            if ((lane & 3) == 0) {
                float* rs4 = (float*)(smem + SM_RS4) + warp_n*64;
                float* dv4 = (float*)(smem + SM_DV4) + warp_n*64;
                float* dh4 = (float*)(smem + SM_DH4) + warp_n*64;
                rs4[rA] = sA;  rs4[rB] = sB;
                dv4[rA] = dVA; dv4[rB] = dVB;
                dh4[rA] = dHA; dh4[rB] = dHB;
            }
        }
        __syncthreads();
        if (tid < 64) {
            const float* rs4 = (const float*)(smem + SM_RS4);
            const float* dv4 = (const float*)(smem + SM_DV4);
            const float* dh4 = (const float*)(smem + SM_DH4);
            float sq = rs4[tid] + rs4[64+tid] + rs4[128+tid] + rs4[192+tid];
            float dv = dv4[tid] + dv4[64+tid] + dv4[128+tid] + dv4[192+tid];
            float dh = dh4[tid] + dh4[64+tid] + dh4[128+tid] + dh4[192+tid];
            float r = rsqrtf(fmaxf(sq, 1e-12f));
            rs[tid] = r;
            gn[tid] = acts[tid] ? dv*r : dh;
        }
        __syncthreads();

        // ---------- epilogue pass 2: normalize + write smem hi/lo (+h gmem at last) --
        #pragma unroll
        for (int mt = 0; mt < 2; mt++) {
            int rA = warp_m*32 + mt*16 + (lane >> 2);
            int rB = rA + 8;
            float rn2[2] = { rs[rA], rs[rB] };
            int   ac2[2] = { acts[rA], acts[rB] };
            int   rr2[2] = { rA, rB };
            #pragma unroll
            for (int half = 0; half < 2; half++) {
                float rn = rn2[half]; int aa = ac2[half]; int row = rr2[half];
                size_t gO = (size_t)(rowBase + row)*ND;
                #pragma unroll
                for (int nt = 0; nt < 8; nt++) {
                    int col = warp_n*64 + nt*8 + 2*(lane & 3);
                    uint32_t off = (uint32_t)row*512 + (uint32_t)((warp_n*8 + nt) ^ r7)*16 + ebyte;
                    float a0 = acc[mt][nt][half*2], a1 = acc[mt][nt][half*2+1];
                    if (aa || first) {
                        float v0 = aa ? a0*rn : 0.f;
                        float v1 = aa ? a1*rn : 0.f;
                        __nv_bfloat16 h0 = __float2bfloat16(v0), h1 = __float2bfloat16(v1);
                        *(__nv_bfloat162*)(smem + SM_AHI + off) = __nv_bfloat162(h0, h1);
                        *(__nv_bfloat162*)(smem + SM_ALO + off) = __nv_bfloat162(
                            __float2bfloat16(v0 - __bfloat162float(h0)),
                            __float2bfloat16(v1 - __bfloat162float(h1)));
                        if (last) *(float2*)(h + gO + col) = make_float2(v0, v1);
                    } else if (last) {
                        __nv_bfloat162 hb = *(__nv_bfloat162*)(smem + SM_AHI + off);
                        __nv_bfloat162 lb = *(__nv_bfloat162*)(smem + SM_ALO + off);
                        *(float2*)(h + gO + col) = make_float2(
                            __bfloat162float(hb.x) + __bfloat162float(lb.x),
                            __bfloat162float(hb.y) + __bfloat162float(lb.y));
                    }
                }
            }
        }
    }
}

// ===================== launch =====================
extern "C" void kernel_launch(void* const* d_in, const int* in_sizes, int n_in,
                              void* d_out, int out_size) {
    const int*   tok  = (const int*)  d_in[0];
    const float* mask = (const float*)d_in[1];
    const float* keys = (const float*)d_in[2];
    const float* emb  = (const float*)d_in[3];
    const float* U    = (const float*)d_in[4];
    const float* V    = (const float*)d_in[5];
    const float* W    = (const float*)d_in[6];
    float* h = (float*)d_out;

    cudaFuncSetAttribute(steps_kernel, cudaFuncAttributeMaxDynamicSharedMemorySize, SMEM_STEPS);

    encode_kernel<<<NB*NS, 256>>>(tok, mask, emb);
    prep_bt_all<<<3*ND, ND>>>(U, V, W);
    split_kernel<<<(NB*NE*ND)/256, 256>>>(keys);
    steps_kernel<<<256, 256, SMEM_STEPS>>>(keys, h);
}

// round 14
// speedup vs baseline: 1.0947x; 1.0947x over previous
#include <cuda_runtime.h>
#include <cuda_bf16.h>
#include <cstdint>
#include <math.h>

#define NB 256
#define NS 32
#define NL 32
#define ND 256
#define NE 64
#define KBIG 768          // Bt columns: [Hi | Lo | Hi-dup(unused)]

// ===================== scratch (device globals; no runtime alloc) =====================
__device__ float g_enc[NB*NS*ND];            // enc[b,s,d]
__device__ float g_eW [NB*NS*ND];            // enc @ W
__device__ float g_kV [NB*NE*ND];            // keys @ V
__device__ int   g_act[NB*NS];
__device__ float g_dek[NB*NE*NS];            // dot(enc_s, keys_row), [row][s]
__device__ __nv_bfloat16 g_Ut[ND*KBIG];      // U^T  [Hi|Lo|Hi]
__device__ __nv_bfloat16 g_Vt[ND*KBIG];      // V^T  [Hi|Lo|Hi]
__device__ __nv_bfloat16 g_Wt[ND*KBIG];      // W^T  [Hi|Lo|Hi]
__device__ __nv_bfloat16 g_kyhi[NB*NE*ND];   // keys split
__device__ __nv_bfloat16 g_kylo[NB*NE*ND];
__device__ __nv_bfloat16 g_enhi[NB*NS*ND];   // enc split
__device__ __nv_bfloat16 g_enlo[NB*NS*ND];

// ===================== PTX wrappers =====================
__device__ __forceinline__ uint32_t smem_u32(const void* p) {
    uint32_t a;
    asm("{ .reg .u64 t; cvta.to.shared.u64 t, %1; cvt.u32.u64 %0, t; }" : "=r"(a) : "l"(p));
    return a;
}
__device__ __forceinline__ void cpa16(uint32_t dst, const void* src) {
    asm volatile("cp.async.cg.shared.global [%0], [%1], 16;" :: "r"(dst), "l"(src));
}
#define CP_COMMIT() asm volatile("cp.async.commit_group;" ::: "memory")
#define CP_WAIT1()  asm volatile("cp.async.wait_group 1;"  ::: "memory")
#define CP_WAIT0()  asm volatile("cp.async.wait_group 0;"  ::: "memory")

__device__ __forceinline__ void ldsm_x4(uint32_t* r, uint32_t addr) {
    asm volatile("ldmatrix.sync.aligned.m8n8.x4.shared.b16 {%0,%1,%2,%3}, [%4];"
        : "=r"(r[0]), "=r"(r[1]), "=r"(r[2]), "=r"(r[3]) : "r"(addr));
}
__device__ __forceinline__ void mma_bf16(float* d, const uint32_t* a, const uint32_t* b) {
    asm volatile("mma.sync.aligned.m16n8k16.row.col.f32.bf16.bf16.f32 "
        "{%0,%1,%2,%3}, {%4,%5,%6,%7}, {%8,%9}, {%0,%1,%2,%3};"
        : "+f"(d[0]), "+f"(d[1]), "+f"(d[2]), "+f"(d[3])
        : "r"(a[0]), "r"(a[1]), "r"(a[2]), "r"(a[3]), "r"(b[0]), "r"(b[1]));
}

// ===================== steps smem layout (128-row CTA, 512 thr, 4-slot ring) =========
#define SM_GATE 0
#define SM_RSQ  512
#define SM_GN   1024
#define SM_ACTS 1536
#define SM_RS4  2048                        // [4][128] floats
#define SM_DV4  4096
#define SM_DH4  6144
#define SM_AHI  8192                        // 128 rows * 512B (xor-swizzled)
#define SM_ALO  (8192 + 65536)
#define SM_RING (8192 + 131072)             // 139264
#define STG     20480
#define SMEM_STEPS (SM_RING + 4*STG)        // 221184

// ===================== encode (vectorized, + bf16 split fold-in) =====================
__global__ __launch_bounds__(256)
void encode_kernel(const int* __restrict__ tok, const float* __restrict__ mask,
                   const float* __restrict__ emb) {
    __shared__ float4 red[4][64];
    const int bs = blockIdx.x, tid = threadIdx.x;
    const int lg = tid >> 6, d4 = tid & 63;
    const int*   t = tok  + (size_t)bs*NL;
    const float* m = mask + (size_t)bs*NL;

    if (tid < 32) {
        float mv = m[tid];
        #pragma unroll
        for (int o = 16; o > 0; o >>= 1) mv += __shfl_xor_sync(0xffffffffu, mv, o);
        if (tid == 0) g_act[bs] = (mv > 0.f) ? 1 : 0;
    }

    float4 acc = make_float4(0.f, 0.f, 0.f, 0.f);
    #pragma unroll
    for (int i = 0; i < 8; i++) {
        int l = lg*8 + i;
        float mv = __ldg(m + l);
        int   tv = __ldg(t + l);
        float4 e = __ldg((const float4*)(emb + (size_t)tv*ND) + d4);
        acc.x += mv*e.x; acc.y += mv*e.y; acc.z += mv*e.z; acc.w += mv*e.w;
    }
    red[lg][d4] = acc;
    __syncthreads();
    if (lg == 0) {
        float4 a = red[0][d4], b = red[1][d4], c = red[2][d4], d = red[3][d4];
        float4 v = make_float4(a.x+b.x+c.x+d.x, a.y+b.y+c.y+d.y,
                               a.z+b.z+c.z+d.z, a.w+b.w+c.w+d.w);
        size_t off = (size_t)bs*ND + d4*4;
        *(float4*)(g_enc + off) = v;
        float vv[4] = {v.x, v.y, v.z, v.w};
        __nv_bfloat16 hb[4], lb[4];
        #pragma unroll
        for (int i = 0; i < 4; i++) {
            hb[i] = __float2bfloat16(vv[i]);
            lb[i] = __float2bfloat16(vv[i] - __bfloat162float(hb[i]));
        }
        *(__nv_bfloat162*)(g_enhi + off)     = __nv_bfloat162(hb[0], hb[1]);
        *(__nv_bfloat162*)(g_enhi + off + 2) = __nv_bfloat162(hb[2], hb[3]);
        *(__nv_bfloat162*)(g_enlo + off)     = __nv_bfloat162(lb[0], lb[1]);
        *(__nv_bfloat162*)(g_enlo + off + 2) = __nv_bfloat162(lb[2], lb[3]);
    }
}

// ===================== prep: Mt[n][k] = [Mhi^T | Mlo^T | Mhi^T] =====================
__global__ void prep_bt_all(const float* __restrict__ U, const float* __restrict__ V,
                            const float* __restrict__ W) {
    int n = blockIdx.x & 255, which = blockIdx.x >> 8, k = threadIdx.x;
    const float* M = (which == 0) ? U : (which == 1) ? V : W;
    __nv_bfloat16* out = (which == 0) ? g_Ut : (which == 1) ? g_Vt : g_Wt;
    float v = M[(size_t)k*ND + n];
    __nv_bfloat16 hi = __float2bfloat16(v);
    __nv_bfloat16 lo = __float2bfloat16(v - __bfloat162float(hi));
    out[(size_t)n*KBIG + k]       = hi;
    out[(size_t)n*KBIG + 256 + k] = lo;
    out[(size_t)n*KBIG + 512 + k] = hi;
}

// ===================== split fp32 -> bf16 hi/lo (keys only) =====================
__global__ void split_kernel(const float* __restrict__ keys) {
    int i = blockIdx.x * blockDim.x + threadIdx.x;
    float v = keys[i];
    __nv_bfloat16 h = __float2bfloat16(v);
    g_kyhi[i] = h;
    g_kylo[i] = __float2bfloat16(v - __bfloat162float(h));
}

// ===================== persistent fused kernel: kV + eW + 32-step recurrence =========
__global__ void __launch_bounds__(512, 1)
steps_kernel(const float* __restrict__ keys, float* __restrict__ h) {
    extern __shared__ char smem[];
    const uint32_t sb = smem_u32(smem);
    const int tid    = threadIdx.x;
    const int lane   = tid & 31;
    const int wid    = tid >> 5;
    const int warp_m = wid >> 2;          // 0..3 -> 32 rows
    const int warp_n = wid & 3;           // 0..3 -> 64 cols
    const int rowBase = blockIdx.x * 128;
    const int bA0 = rowBase >> 6;         // first of 2 b's this CTA owns
    const int PTOT = 16 + (NS - 1) * 8;   // pairs: 8 Vt + 8 Wt + 248 Ut = 264

    float* gs   = (float*)(smem + SM_GATE);
    float* rs   = (float*)(smem + SM_RSQ);
    float* gn   = (float*)(smem + SM_GN);
    int*   acts = (int*)  (smem + SM_ACTS);

    // ---- B stream: chunk c (= 2*pair + parity); even=Hi, odd=Lo; slot c&3 ----
    auto load_chunk = [&](int c) {
        int q = c & 15;
        int kk = (q >> 1) * 32;
        const __nv_bfloat16* mat = (c < 16) ? g_Vt : (c < 32) ? g_Wt : g_Ut;
        const __nv_bfloat16* bsrc = mat + ((q & 1) ? (256 + kk) : kk);
        uint32_t base = sb + SM_RING + (uint32_t)(c & 3)*STG;
        #pragma unroll
        for (int i = 0; i < 2; i++) {
            int idx = tid + i*512, row = idx >> 2, seg = idx & 3;
            cpa16(base + row*80 + seg*16, bsrc + (size_t)row*KBIG + seg*8);
        }
    };
    // one commit per pair (2 chunks)
    auto load_pair = [&](int p) {
        load_chunk(2*p);
        load_chunk(2*p + 1);
        CP_COMMIT();
    };

    // ---- A smem loader (plain LDG/STS), nrows = 128 or 64 ----
    auto load_A = [&](const __nv_bfloat16* srcHi, const __nv_bfloat16* srcLo, int niter) {
        for (int i = 0; i < niter; i++) {
            int idx = tid + i*512;
            int row = idx >> 5, seg = idx & 31;
            uint32_t dst = (uint32_t)row*512 + (uint32_t)((seg ^ (row & 7))*16);
            *(uint4*)(smem + SM_AHI + dst) = *(const uint4*)(srcHi + (size_t)row*ND + seg*8);
            *(uint4*)(smem + SM_ALO + dst) = *(const uint4*)(srcLo + (size_t)row*ND + seg*8);
        }
    };

    int pnext = 0;
    load_pair(pnext); pnext++;            // pair 0 in flight before phase 0

    // ---------- phase 0: g_dek[row][s] = dot(enc_s, keys_row) (overlaps prefetch) ----
    {
        int r = tid >> 2, part = tid & 3;
        int grow = rowBase + r, b = grow >> 6;
        float4 ky[16];
        const float4* kp = (const float4*)(keys + (size_t)grow*ND + part*64);
        #pragma unroll
        for (int i = 0; i < 16; i++) ky[i] = kp[i];
        for (int s = 0; s < NS; s++) {
            const float4* ep = (const float4*)(g_enc + ((size_t)b*NS + s)*ND + part*64);
            float d = 0.f;
            #pragma unroll
            for (int i = 0; i < 16; i++) {
                float4 e = ep[i];
                d += ky[i].x*e.x + ky[i].y*e.y + ky[i].z*e.z + ky[i].w*e.w;
            }
            d += __shfl_xor_sync(0xffffffffu, d, 1);
            d += __shfl_xor_sync(0xffffffffu, d, 2);
            if (part == 0) g_dek[(size_t)grow*NS + s] = d;
        }
        if (tid < 128) gn[tid] = 0.f;
    }

    // ---- per-lane constants ----
    const int lane7 = lane & 7;
    const int sel2  = lane >> 4;
    const uint32_t arow = (uint32_t)(warp_m*32 + ((lane >> 3) & 1)*8 + lane7) * 512;
    const uint32_t boff4 = (uint32_t)(((lane >> 4)*8 + lane7)*80 + ((lane >> 3) & 1)*16);
    const int r7 = (lane >> 2) & 7;
    const uint32_t ebyte = (uint32_t)((lane & 3)*4);

    float acc[2][8][4];
    uint32_t ahc[2][8];                   // A-hi fragments carried Hi->Lo chunk
    auto zero_acc = [&]() {
        #pragma unroll
        for (int mt = 0; mt < 2; mt++)
            #pragma unroll
            for (int nt = 0; nt < 8; nt++)
                #pragma unroll
                for (int q = 0; q < 4; q++) acc[mt][nt][q] = 0.f;
    };

    auto compute = [&](int c) {
        const int q = c & 15;
        const int kkidx = q >> 1;
        const bool isHi = !(q & 1);
        uint32_t bB = sb + SM_RING + (uint32_t)(c & 3)*STG + (warp_n*64)*80 + boff4;
        const int kseg0 = kkidx*4 + sel2;
        #pragma unroll
        for (int k2 = 0; k2 < 2; ++k2) {
            const uint32_t kb = (uint32_t)k2*32;
            uint32_t bq[16];
            #pragma unroll
            for (int np = 0; np < 4; np++) ldsm_x4(&bq[np*4], bB + np*1280 + kb);
            if (isHi) {
                const uint32_t seg = (uint32_t)((kseg0 + k2*2) ^ lane7) * 16;
                uint32_t aHa = sb + SM_AHI + arow + seg;
                ldsm_x4(&ahc[k2][0], aHa);
                ldsm_x4(&ahc[k2][4], aHa + 8192);
                #pragma unroll
                for (int np = 0; np < 4; np++) {
                    mma_bf16(acc[0][2*np],   &ahc[k2][0], &bq[np*4]);
                    mma_bf16(acc[0][2*np+1], &ahc[k2][0], &bq[np*4+2]);
                    mma_bf16(acc[1][2*np],   &ahc[k2][4], &bq[np*4]);
                    mma_bf16(acc[1][2*np+1], &ahc[k2][4], &bq[np*4+2]);
                }
                uint32_t aLa = sb + SM_ALO + arow + seg;
                uint32_t al[8];
                ldsm_x4(al,     aLa);
                ldsm_x4(al + 4, aLa + 8192);
                #pragma unroll
                for (int np = 0; np < 4; np++) {
                    mma_bf16(acc[0][2*np],   al,     &bq[np*4]);
                    mma_bf16(acc[0][2*np+1], al,     &bq[np*4+2]);
                    mma_bf16(acc[1][2*np],   al + 4, &bq[np*4]);
                    mma_bf16(acc[1][2*np+1], al + 4, &bq[np*4+2]);
                }
            } else {
                #pragma unroll
                for (int np = 0; np < 4; np++) {
                    mma_bf16(acc[0][2*np],   &ahc[k2][0], &bq[np*4]);
                    mma_bf16(acc[0][2*np+1], &ahc[k2][0], &bq[np*4+2]);
                    mma_bf16(acc[1][2*np],   &ahc[k2][4], &bq[np*4]);
                    mma_bf16(acc[1][2*np+1], &ahc[k2][4], &bq[np*4+2]);
                }
            }
        }
    };

    // pair schedule: sync -> issue pair p+1 -> wait(pair p) -> compute Hi,Lo of pair p
    auto run8 = [&](int p0) {
        for (int i = 0; i < 8; ++i) {
            const int p = p0 + i;
            __syncthreads();                   // pair p-1's slots consumed; safe reuse
            if (pnext < PTOT && pnext == p + 1) { load_pair(pnext); pnext++; }
            const int pend = pnext - 1 - p;
            if (pend >= 1) CP_WAIT1(); else CP_WAIT0();
            compute(2*p);
            compute(2*p + 1);
        }
    };

    // ---------- phase 1: kV = keys @ V for this CTA's 128 rows ----------
    load_A(g_kyhi + (size_t)rowBase*ND, g_kylo + (size_t)rowBase*ND, 8);
    zero_acc();
    run8(0);
    __syncthreads();
    #pragma unroll
    for (int mt = 0; mt < 2; mt++) {
        int rA = warp_m*32 + mt*16 + (lane >> 2);
        int rB = rA + 8;
        size_t gOA = (size_t)(rowBase + rA)*ND;
        size_t gOB = (size_t)(rowBase + rB)*ND;
        #pragma unroll
        for (int nt = 0; nt < 8; nt++) {
            int col = warp_n*64 + nt*8 + 2*(lane & 3);
            *(float2*)(g_kV + gOA + col) = make_float2(acc[mt][nt][0], acc[mt][nt][1]);
            *(float2*)(g_kV + gOB + col) = make_float2(acc[mt][nt][2], acc[mt][nt][3]);
        }
    }

    // ---------- phase 2: eW = enc @ W for this CTA's 64 enc rows ----------
    __syncthreads();                      // kV stores done before A tile overwritten
    load_A(g_enhi + (size_t)(bA0*32)*ND, g_enlo + (size_t)(bA0*32)*ND, 4);
    zero_acc();
    run8(8);
    __syncthreads();
    if (warp_m < 2) {
        #pragma unroll
        for (int mt = 0; mt < 2; mt++) {
            int rA = warp_m*32 + mt*16 + (lane >> 2);
            int rB = rA + 8;
            size_t gOA = (size_t)(bA0*32 + rA)*ND;
            size_t gOB = (size_t)(bA0*32 + rB)*ND;
            #pragma unroll
            for (int nt = 0; nt < 8; nt++) {
                int col = warp_n*64 + nt*8 + 2*(lane & 3);
                *(float2*)(g_eW + gOA + col) = make_float2(acc[mt][nt][0], acc[mt][nt][1]);
                *(float2*)(g_eW + gOB + col) = make_float2(acc[mt][nt][2], acc[mt][nt][3]);
            }
        }
    }

    // ---------- phase 3: the 32-step recurrence ----------
    for (int s = 0; s < NS; ++s) {
        const bool first = (s == 0);
        const bool last  = (s == NS - 1);
        __syncthreads();
        if (tid < 128) {
            int grow = rowBase + tid;
            int b = grow >> 6;
            gs[tid]   = 1.f / (1.f + expf(-(gn[tid] + g_dek[(size_t)grow*NS + s])));
            acts[tid] = g_act[b*NS + s];
        }

        zero_acc();

        if (!first) {
            run8(16 + (s - 1)*8);
        } else {
            __syncthreads();
        }

        // ---------- epilogue pass 1 (h state from persistent smem) ----------
        const int sn = (s + 1 < NS) ? s + 1 : NS - 1;
        #pragma unroll
        for (int mt = 0; mt < 2; mt++) {
            int rA = warp_m*32 + mt*16 + (lane >> 2);
            int rB = rA + 8;
            int gA = rowBase + rA, gB = rowBase + rB;
            int bA = gA >> 6;
            const float* kvA = g_kV + (size_t)gA*ND;
            const float* kvB = g_kV + (size_t)gB*ND;
            const float* ewR = g_eW  + ((size_t)bA*NS + s )*ND;
            const float* enN = g_enc + ((size_t)bA*NS + sn)*ND;
            float gateA = gs[rA], gateB = gs[rB];
            float sA = 0.f, sB = 0.f;
            float dVA = 0.f, dVB = 0.f, dHA = 0.f, dHB = 0.f;
            #pragma unroll
            for (int nt = 0; nt < 8; nt++) {
                int col = warp_n*64 + nt*8 + 2*(lane & 3);
                const uint32_t seg = (uint32_t)((warp_n*8 + nt) ^ r7) * 16;
                float2 en = *(const float2*)(enN + col);
                float2 ew = *(const float2*)(ewR + col);
                float2 kv, ho;
                kv = *(const float2*)(kvA + col);
                if (first) ho = make_float2(0.f, 0.f);
                else {
                    uint32_t offA = (uint32_t)rA*512 + seg + ebyte;
                    __nv_bfloat162 hb = *(__nv_bfloat162*)(smem + SM_AHI + offA);
                    __nv_bfloat162 lb = *(__nv_bfloat162*)(smem + SM_ALO + offA);
                    ho = make_float2(__bfloat162float(hb.x) + __bfloat162float(lb.x),
                                     __bfloat162float(hb.y) + __bfloat162float(lb.y));
                }
                float v0 = fmaxf(acc[mt][nt][0] + kv.x + ew.x, 0.f);
                float v1 = fmaxf(acc[mt][nt][1] + kv.y + ew.y, 0.f);
                float h0 = ho.x + gateA*v0, h1 = ho.y + gateA*v1;
                acc[mt][nt][0] = h0; acc[mt][nt][1] = h1;
                sA  += h0*h0 + h1*h1;
                dVA += en.x*h0 + en.y*h1;
                dHA += en.x*ho.x + en.y*ho.y;
                kv = *(const float2*)(kvB + col);
                if (first) ho = make_float2(0.f, 0.f);
                else {
                    uint32_t offB = (uint32_t)rB*512 + seg + ebyte;
                    __nv_bfloat162 hb = *(__nv_bfloat162*)(smem + SM_AHI + offB);
                    __nv_bfloat162 lb = *(__nv_bfloat162*)(smem + SM_ALO + offB);
                    ho = make_float2(__bfloat162float(hb.x) + __bfloat162float(lb.x),
                                     __bfloat162float(hb.y) + __bfloat162float(lb.y));
                }
                float w0 = fmaxf(acc[mt][nt][2] + kv.x + ew.x, 0.f);
                float w1 = fmaxf(acc[mt][nt][3] + kv.y + ew.y, 0.f);
                float h2 = ho.x + gateB*w0, h3 = ho.y + gateB*w1;
                acc[mt][nt][2] = h2; acc[mt][nt][3] = h3;
                sB  += h2*h2 + h3*h3;
                dVB += en.x*h2 + en.y*h3;
                dHB += en.x*ho.x + en.y*ho.y;
            }
            #pragma unroll
            for (int o = 1; o <= 2; o <<= 1) {
                sA  += __shfl_xor_sync(0xffffffffu, sA,  o);
                sB  += __shfl_xor_sync(0xffffffffu, sB,  o);
                dVA += __shfl_xor_sync(0xffffffffu, dVA, o);
                dVB += __shfl_xor_sync(0xffffffffu, dVB, o);
                dHA += __shfl_xor_sync(0xffffffffu, dHA, o);
                dHB += __shfl_xor_sync(0xffffffffu, dHB, o);
            }
            if ((lane & 3) == 0) {
                float* rs4 = (float*)(smem + SM_RS4) + warp_n*128;
                float* dv4 = (float*)(smem + SM_DV4) + warp_n*128;
                float* dh4 = (float*)(smem + SM_DH4) + warp_n*128;
                rs4[rA] = sA;  rs4[rB] = sB;
                dv4[rA] = dVA; dv4[rB] = dVB;
                dh4[rA] = dHA; dh4[rB] = dHB;
            }
        }
        __syncthreads();
        if (tid < 128) {
            const float* rs4 = (const float*)(smem + SM_RS4);
            const float* dv4 = (const float*)(smem + SM_DV4);
            const float* dh4 = (const float*)(smem + SM_DH4);
            float sq = rs4[tid] + rs4[128+tid] + rs4[256+tid] + rs4[384+tid];
            float dv = dv4[tid] + dv4[128+tid] + dv4[256+tid] + dv4[384+tid];
            float dh = dh4[tid] + dh4[128+tid] + dh4[256+tid] + dh4[384+tid];
            float r = rsqrtf(fmaxf(sq, 1e-12f));
            rs[tid] = r;
            gn[tid] = acts[tid] ? dv*r : dh;
        }
        __syncthreads();

        // ---------- epilogue pass 2: normalize + write smem hi/lo (+h gmem at last) --
        #pragma unroll
        for (int mt = 0; mt < 2; mt++) {
            int rA = warp_m*32 + mt*16 + (lane >> 2);
            int rB = rA + 8;
            float rn2[2] = { rs[rA], rs[rB] };
            int   ac2[2] = { acts[rA], acts[rB] };
            int   rr2[2] = { rA, rB };
            #pragma unroll
            for (int half = 0; half < 2; half++) {
                float rn = rn2[half]; int aa = ac2[half]; int row = rr2[half];
                size_t gO = (size_t)(rowBase + row)*ND;
                #pragma unroll
                for (int nt = 0; nt < 8; nt++) {
                    int col = warp_n*64 + nt*8 + 2*(lane & 3);
                    uint32_t off = (uint32_t)row*512 + (uint32_t)((warp_n*8 + nt) ^ r7)*16 + ebyte;
                    float a0 = acc[mt][nt][half*2], a1 = acc[mt][nt][half*2+1];
                    if (aa || first) {
                        float v0 = aa ? a0*rn : 0.f;
                        float v1 = aa ? a1*rn : 0.f;
                        __nv_bfloat16 h0 = __float2bfloat16(v0), h1 = __float2bfloat16(v1);
                        *(__nv_bfloat162*)(smem + SM_AHI + off) = __nv_bfloat162(h0, h1);
                        *(__nv_bfloat162*)(smem + SM_ALO + off) = __nv_bfloat162(
                            __float2bfloat16(v0 - __bfloat162float(h0)),
                            __float2bfloat16(v1 - __bfloat162float(h1)));
                        if (last) *(float2*)(h + gO + col) = make_float2(v0, v1);
                    } else if (last) {
                        __nv_bfloat162 hb = *(__nv_bfloat162*)(smem + SM_AHI + off);
                        __nv_bfloat162 lb = *(__nv_bfloat162*)(smem + SM_ALO + off);
                        *(float2*)(h + gO + col) = make_float2(
                            __bfloat162float(hb.x) + __bfloat162float(lb.x),
                            __bfloat162float(hb.y) + __bfloat162float(lb.y));
                    }
                }
            }
        }
    }
}

// ===================== launch =====================
extern "C" void kernel_launch(void* const* d_in, const int* in_sizes, int n_in,
                              void* d_out, int out_size) {
    const int*   tok  = (const int*)  d_in[0];
    const float* mask = (const float*)d_in[1];
    const float* keys = (const float*)d_in[2];
    const float* emb  = (const float*)d_in[3];
    const float* U    = (const float*)d_in[4];
    const float* V    = (const float*)d_in[5];
    const float* W    = (const float*)d_in[6];
    float* h = (float*)d_out;

    cudaFuncSetAttribute(steps_kernel, cudaFuncAttributeMaxDynamicSharedMemorySize, SMEM_STEPS);

    encode_kernel<<<NB*NS, 256>>>(tok, mask, emb);
    prep_bt_all<<<3*ND, ND>>>(U, V, W);
    split_kernel<<<(NB*NE*ND)/256, 256>>>(keys);
    steps_kernel<<<128, 512, SMEM_STEPS>>>(keys, h);
}